// round 2
// baseline (speedup 1.0000x reference)
#include <cuda_runtime.h>
#include <stdint.h>

#define D       256
#define MITEMS  16
#define TPB     256
#define RPB     256          // one row per thread
#define QS      260          // transposed q-tile stride: 260 % 32 == 4 -> conflict-free staging
#define NEG_BIG (-1e30f)

// Dynamic smem layout (floats):
//   mem_rm : [0, 4096)        16 x 256 row-major (blend source)
//   mem_t  : [4096, 8192)     256 x 16 transposed (dot-phase broadcast)
//   qs     : [8192, 10272)    8 x 260 transposed q tile [c][row]
//   pw     : [10272, 11296)   256 x 4 softmax weights
//   pidx   : [11296, 11552)   256 packed top-4 indices (int)
#define SMEM_FLOATS 11552
#define SMEM_BYTES  (SMEM_FLOATS * 4)

__global__ void __launch_bounds__(TPB, 4) epm_kernel(
    const float* __restrict__ q,
    const float* __restrict__ mem,
    float* __restrict__ out_ret,
    float* __restrict__ out_max,
    int nrows)
{
    extern __shared__ __align__(16) float sh[];
    float* mem_rm = sh;
    float* mem_t  = sh + 4096;
    float* qs     = sh + 8192;
    float* pw     = sh + 10272;
    int*   pidx   = (int*)(sh + 11296);

    const int tid = threadIdx.x;
    const int blockRow = blockIdx.x * RPB;

    // ---- Load memory bank into smem (both layouts) ----
    #pragma unroll
    for (int i = 0; i < (MITEMS * D) / TPB; i++) {   // 16 iters
        int idx = tid + TPB * i;
        float v = mem[idx];
        mem_rm[idx] = v;
        mem_t[(idx & (D - 1)) * MITEMS + (idx >> 8)] = v;
    }
    // ordered before first use by the __syncthreads inside the ct loop

    // ---- Dot phase: 1 row/thread x 16 items, column tiles of 8 ----
    float acc[MITEMS];
    #pragma unroll
    for (int m = 0; m < MITEMS; m++) acc[m] = 0.0f;
    float ssq = 0.0f;

    const int ccw = tid & 7;       // staging column within 8-wide tile
    const int rw0 = tid >> 3;      // staging base row (0..31), step 32
    const int nr1 = nrows - 1;

    for (int ct = 0; ct < D / 8; ct++) {   // 32 tiles
        __syncthreads();                   // qs free from previous tile's readers
        #pragma unroll
        for (int j = 0; j < 8; j++) {
            int rl = rw0 + 32 * j;                    // local row 0..255
            int rg = blockRow + rl;
            rg = rg < nr1 ? rg : nr1;                 // clamp (full blocks unaffected)
            qs[ccw * QS + rl] = q[(size_t)rg * D + ct * 8 + ccw];
        }
        __syncthreads();

        #pragma unroll
        for (int cc = 0; cc < 8; cc++) {
            int c = ct * 8 + cc;
            float qv = qs[cc * QS + tid];             // consecutive lanes -> conflict-free
            const float4* mt = (const float4*)(mem_t + c * MITEMS);
            float4 m0 = mt[0], m1 = mt[1], m2 = mt[2], m3 = mt[3];  // broadcast
            ssq += qv * qv;
            acc[ 0] += m0.x * qv;  acc[ 1] += m0.y * qv;
            acc[ 2] += m0.z * qv;  acc[ 3] += m0.w * qv;
            acc[ 4] += m1.x * qv;  acc[ 5] += m1.y * qv;
            acc[ 6] += m1.z * qv;  acc[ 7] += m1.w * qv;
            acc[ 8] += m2.x * qv;  acc[ 9] += m2.y * qv;
            acc[10] += m2.z * qv;  acc[11] += m2.w * qv;
            acc[12] += m3.x * qv;  acc[13] += m3.y * qv;
            acc[14] += m3.z * qv;  acc[15] += m3.w * qv;
        }
    }

    // ---- Epilogue: normalize, top-4 (first-index tie-break), softmax ----
    {
        float inv = rsqrtf(fmaxf(ssq, 1e-24f)) * 10.0f;   // (1/|q|)/tau, mem rows unit-norm
        float s[MITEMS];
        #pragma unroll
        for (int m = 0; m < MITEMS; m++) s[m] = acc[m] * inv;

        float bw[4]; int bi[4];
        #pragma unroll
        for (int k = 0; k < 4; k++) {
            float best = NEG_BIG; int b = 0;
            #pragma unroll
            for (int m = 0; m < MITEMS; m++)
                if (s[m] > best) { best = s[m]; b = m; }
            bw[k] = best; bi[k] = b;
            #pragma unroll
            for (int m = 0; m < MITEMS; m++)
                s[m] = (m == b) ? NEG_BIG : s[m];
        }

        float e1 = __expf(bw[1] - bw[0]);
        float e2 = __expf(bw[2] - bw[0]);
        float e3 = __expf(bw[3] - bw[0]);
        float rden = 1.0f / (1.0f + e1 + e2 + e3);

        pw[tid * 4 + 0] = rden;
        pw[tid * 4 + 1] = e1 * rden;
        pw[tid * 4 + 2] = e2 * rden;
        pw[tid * 4 + 3] = e3 * rden;
        pidx[tid] = bi[0] | (bi[1] << 4) | (bi[2] << 8) | (bi[3] << 12);

        int row_g = blockRow + tid;
        if (row_g < nrows) out_max[row_g] = bw[0];
    }
    __syncthreads();

    // ---- Blend: warp-per-row (lanes share idx -> dense conflict-free LDS.128) ----
    const int wid  = tid >> 5;
    const int lane = tid & 31;
    #pragma unroll 2
    for (int i = 0; i < RPB / 8; i++) {      // 32 rows per warp
        int row_l = wid * (RPB / 8) + i;
        int row_g = blockRow + row_l;
        float4 w4 = *(const float4*)(pw + row_l * 4);
        int pk = pidx[row_l];
        const float4* b0 = (const float4*)(mem_rm + ((pk      ) & 15) * D);
        const float4* b1 = (const float4*)(mem_rm + ((pk >> 4 ) & 15) * D);
        const float4* b2 = (const float4*)(mem_rm + ((pk >> 8 ) & 15) * D);
        const float4* b3 = (const float4*)(mem_rm + ((pk >> 12) & 15) * D);
        float4* orow = (float4*)(out_ret + (size_t)row_g * D);
        bool ok = row_g < nrows;
        #pragma unroll
        for (int t = 0; t < 2; t++) {
            int c4 = lane + 32 * t;          // float4 column 0..63
            float4 a0 = b0[c4], a1 = b1[c4], a2 = b2[c4], a3 = b3[c4];
            float4 o;
            o.x = w4.x * a0.x + w4.y * a1.x + w4.z * a2.x + w4.w * a3.x;
            o.y = w4.x * a0.y + w4.y * a1.y + w4.z * a2.y + w4.w * a3.y;
            o.z = w4.x * a0.z + w4.y * a1.z + w4.z * a2.z + w4.w * a3.z;
            o.w = w4.x * a0.w + w4.y * a1.w + w4.z * a2.w + w4.w * a3.w;
            if (ok) orow[c4] = o;
        }
    }
}

extern "C" void kernel_launch(void* const* d_in, const int* in_sizes, int n_in,
                              void* d_out, int out_size)
{
    const float* q   = (const float*)d_in[0];
    const float* mem = (const float*)d_in[1];
    int nrows = in_sizes[0] / D;              // 131072
    float* out_ret = (float*)d_out;
    float* out_max = out_ret + (size_t)nrows * D;

    cudaFuncSetAttribute(epm_kernel,
                         cudaFuncAttributeMaxDynamicSharedMemorySize, SMEM_BYTES);

    int grid = (nrows + RPB - 1) / RPB;       // 512
    epm_kernel<<<grid, TPB, SMEM_BYTES>>>(q, mem, out_ret, out_max, nrows);
}

// round 3
// speedup vs baseline: 1.0564x; 1.0564x over previous
#include <cuda_runtime.h>
#include <stdint.h>

#define D       256
#define MITEMS  16
#define TPB     128
#define RPT     2
#define RPB     256            // rows per block
#define QS      260            // qs row stride (words): 260%32==4 -> conflict-free
#define QSBUF   (8 * QS)       // one tile buffer = 2080 floats
#define NEG_BIG (-1e30f)

typedef unsigned long long u64;

// smem layout (floats):
//   mem_rm : [0, 4096)        16 x 256 row-major (blend source)
//   mem_t  : [4096, 8192)     256 x 16 transposed (dot broadcast; item pairs packed)
//   qs     : [8192, 12352)    2 x (8 x 260) double-buffered transposed q tiles
//   pw     : [12352, 13376)   256 x 4 softmax weights
//   pidx   : [13376, 13632)   256 packed top-4 indices
#define SMEM_FLOATS 13632
#define SMEM_BYTES  (SMEM_FLOATS * 4)

__device__ __forceinline__ u64 pack2(float lo, float hi) {
    u64 r; asm("mov.b64 %0, {%1, %2};" : "=l"(r) : "f"(lo), "f"(hi)); return r;
}
__device__ __forceinline__ void unpack2(u64 v, float& lo, float& hi) {
    asm("mov.b64 {%0, %1}, %2;" : "=f"(lo), "=f"(hi) : "l"(v));
}
#define FMA2(d, a, b) asm("fma.rn.f32x2 %0, %1, %2, %0;" : "+l"(d) : "l"(a), "l"(b))

__global__ void __launch_bounds__(TPB, 4) epm_kernel(
    const float* __restrict__ q,
    const float* __restrict__ mem,
    float* __restrict__ out_ret,
    float* __restrict__ out_max,
    int nrows)
{
    extern __shared__ __align__(16) float sh[];
    float* mem_rm = sh;
    float* mem_t  = sh + 4096;
    float* qs     = sh + 8192;
    float* pw     = sh + 12352;
    int*   pidx   = (int*)(sh + 13376);

    const int tid = threadIdx.x;
    const int blockRow = blockIdx.x * RPB;
    const int nr1 = nrows - 1;

    // ---- Load memory bank into smem (both layouts) ----
    #pragma unroll
    for (int i = 0; i < (MITEMS * D) / TPB; i++) {   // 32 iters
        int idx = tid + TPB * i;
        float v = mem[idx];
        mem_rm[idx] = v;
        mem_t[(idx & (D - 1)) * MITEMS + (idx >> 8)] = v;
    }

    // ---- Staging geometry: thread loads float4 (4 cols) for 4 rows per tile ----
    const int cg   = tid & 1;          // column-group (0..1) of 4 cols within 8-col tile
    const int rw0  = tid >> 1;         // base row (0..63), step 64

    // accumulators: item pairs packed (f32x2), per row
    u64 accA[8], accB[8], ssq2;
    #pragma unroll
    for (int p = 0; p < 8; p++) { accA[p] = 0ull; accB[p] = 0ull; }
    ssq2 = 0ull;

    float4 st[4];   // prefetch registers

    // prologue: load + stage tile 0
    #pragma unroll
    for (int j = 0; j < 4; j++) {
        int rl = rw0 + 64 * j;
        int rg = blockRow + rl; rg = rg < nr1 ? rg : nr1;
        st[j] = *(const float4*)(q + (size_t)rg * D + 4 * cg);
    }
    {
        float* buf = qs;
        #pragma unroll
        for (int j = 0; j < 4; j++) {
            int rl = rw0 + 64 * j;
            buf[(4 * cg + 0) * QS + rl] = st[j].x;
            buf[(4 * cg + 1) * QS + rl] = st[j].y;
            buf[(4 * cg + 2) * QS + rl] = st[j].z;
            buf[(4 * cg + 3) * QS + rl] = st[j].w;
        }
    }
    __syncthreads();

    for (int ct = 0; ct < D / 8; ct++) {   // 32 tiles of 8 dims
        // prefetch next tile's global data (issued before compute -> latency hidden)
        bool more = (ct + 1) < D / 8;
        if (more) {
            #pragma unroll
            for (int j = 0; j < 4; j++) {
                int rl = rw0 + 64 * j;
                int rg = blockRow + rl; rg = rg < nr1 ? rg : nr1;
                st[j] = *(const float4*)(q + (size_t)rg * D + (ct + 1) * 8 + 4 * cg);
            }
        }

        // compute on buffer ct&1
        const float* qb = qs + (ct & 1) * QSBUF;
        #pragma unroll
        for (int cc = 0; cc < 8; cc++) {
            float2 qp = *(const float2*)(qb + cc * QS + 2 * tid);
            u64 qa = pack2(qp.x, qp.x);
            u64 qb2 = pack2(qp.y, qp.y);
            u64 qq = pack2(qp.x, qp.y);
            const ulonglong2* mt = (const ulonglong2*)(mem_t + (ct * 8 + cc) * MITEMS);
            ulonglong2 v0 = mt[0], v1 = mt[1], v2 = mt[2], v3 = mt[3];
            u64 mp[8] = {v0.x, v0.y, v1.x, v1.y, v2.x, v2.y, v3.x, v3.y};
            FMA2(ssq2, qq, qq);
            #pragma unroll
            for (int p = 0; p < 8; p++) {
                FMA2(accA[p], mp[p], qa);
                FMA2(accB[p], mp[p], qb2);
            }
        }

        // stage next tile into the other buffer (its previous readers done at last sync)
        if (more) {
            float* buf = qs + ((ct + 1) & 1) * QSBUF;
            #pragma unroll
            for (int j = 0; j < 4; j++) {
                int rl = rw0 + 64 * j;
                buf[(4 * cg + 0) * QS + rl] = st[j].x;
                buf[(4 * cg + 1) * QS + rl] = st[j].y;
                buf[(4 * cg + 2) * QS + rl] = st[j].z;
                buf[(4 * cg + 3) * QS + rl] = st[j].w;
            }
        }
        __syncthreads();
    }

    // ---- Epilogue: 2 rows per thread ----
    float ssq[2];
    unpack2(ssq2, ssq[0], ssq[1]);
    #pragma unroll
    for (int r = 0; r < RPT; r++) {
        float s[MITEMS];
        #pragma unroll
        for (int p = 0; p < 8; p++) {
            float lo, hi;
            unpack2(r == 0 ? accA[p] : accB[p], lo, hi);
            s[2 * p] = lo; s[2 * p + 1] = hi;
        }
        float inv = rsqrtf(fmaxf(ssq[r], 1e-24f)) * 10.0f;  // (1/|q|)/tau; mem unit-norm
        #pragma unroll
        for (int m = 0; m < MITEMS; m++) s[m] *= inv;

        float bw[4]; int bi[4];
        #pragma unroll
        for (int k = 0; k < 4; k++) {
            float best = NEG_BIG; int b = 0;
            #pragma unroll
            for (int m = 0; m < MITEMS; m++)
                if (s[m] > best) { best = s[m]; b = m; }   // strict > : first index wins ties
            bw[k] = best; bi[k] = b;
            #pragma unroll
            for (int m = 0; m < MITEMS; m++)
                s[m] = (m == b) ? NEG_BIG : s[m];
        }

        float e1 = __expf(bw[1] - bw[0]);
        float e2 = __expf(bw[2] - bw[0]);
        float e3 = __expf(bw[3] - bw[0]);
        float rden = 1.0f / (1.0f + e1 + e2 + e3);

        int row_l = 2 * tid + r;
        pw[row_l * 4 + 0] = rden;
        pw[row_l * 4 + 1] = e1 * rden;
        pw[row_l * 4 + 2] = e2 * rden;
        pw[row_l * 4 + 3] = e3 * rden;
        pidx[row_l] = bi[0] | (bi[1] << 4) | (bi[2] << 8) | (bi[3] << 12);

        int row_g = blockRow + row_l;
        if (row_g < nrows) out_max[row_g] = bw[0];
    }
    __syncthreads();

    // ---- Blend: warp-per-row (lanes share idx -> conflict-free broadcast-free LDS) ----
    const int wid  = tid >> 5;
    const int lane = tid & 31;
    #pragma unroll 2
    for (int i = 0; i < RPB / 4; i++) {          // 64 rows per warp
        int row_l = wid * (RPB / 4) + i;
        int row_g = blockRow + row_l;
        float4 w4 = *(const float4*)(pw + row_l * 4);
        int pk = pidx[row_l];
        const float4* b0 = (const float4*)(mem_rm + ((pk      ) & 15) * D);
        const float4* b1 = (const float4*)(mem_rm + ((pk >> 4 ) & 15) * D);
        const float4* b2 = (const float4*)(mem_rm + ((pk >> 8 ) & 15) * D);
        const float4* b3 = (const float4*)(mem_rm + ((pk >> 12) & 15) * D);
        float4* orow = (float4*)(out_ret + (size_t)row_g * D);
        bool ok = row_g < nrows;
        #pragma unroll
        for (int t = 0; t < 2; t++) {
            int c4 = lane + 32 * t;
            float4 a0 = b0[c4], a1 = b1[c4], a2 = b2[c4], a3 = b3[c4];
            float4 o;
            o.x = w4.x * a0.x + w4.y * a1.x + w4.z * a2.x + w4.w * a3.x;
            o.y = w4.x * a0.y + w4.y * a1.y + w4.z * a2.y + w4.w * a3.y;
            o.z = w4.x * a0.z + w4.y * a1.z + w4.z * a2.z + w4.w * a3.z;
            o.w = w4.x * a0.w + w4.y * a1.w + w4.z * a2.w + w4.w * a3.w;
            if (ok) orow[c4] = o;
        }
    }
}

extern "C" void kernel_launch(void* const* d_in, const int* in_sizes, int n_in,
                              void* d_out, int out_size)
{
    const float* q   = (const float*)d_in[0];
    const float* mem = (const float*)d_in[1];
    int nrows = in_sizes[0] / D;              // 131072
    float* out_ret = (float*)d_out;
    float* out_max = out_ret + (size_t)nrows * D;

    cudaFuncSetAttribute(epm_kernel,
                         cudaFuncAttributeMaxDynamicSharedMemorySize, SMEM_BYTES);

    int grid = (nrows + RPB - 1) / RPB;       // 512
    epm_kernel<<<grid, TPB, SMEM_BYTES>>>(q, mem, out_ret, out_max, nrows);
}

// round 4
// speedup vs baseline: 1.1765x; 1.1136x over previous
#include <cuda_runtime.h>
#include <stdint.h>

#define D       256
#define MITEMS  16
#define TPB     256
#define ROWS    256          // rows per block (thread = row)
#define CHUNK   32           // dims per tile
#define NCH     (D / CHUNK)  // 8
#define QSTR    33           // q smem row stride: bank = row + c (conflict-free)
#define QBUF    (ROWS * QSTR)   // 8448 floats per buffer
#define WSTR    20           // W row stride: 16B-aligned, ~4-way write conflicts only
#define NEG_BIG (-1e30f)

// smem floats: qs 2*8448 = 16896 | mem_t 4096 | W 256*20 = 5120  -> 26112 (104448 B)
#define SM_MT   (2 * QBUF)
#define SM_W    (SM_MT + MITEMS * D)
#define SMEM_FLOATS (SM_W + ROWS * WSTR)
#define SMEM_BYTES  (SMEM_FLOATS * 4)

typedef unsigned long long u64;

__device__ __forceinline__ u64 pack2(float lo, float hi) {
    u64 r; asm("mov.b64 %0, {%1, %2};" : "=l"(r) : "f"(lo), "f"(hi)); return r;
}
__device__ __forceinline__ void unpack2(u64 v, float& lo, float& hi) {
    asm("mov.b64 {%0, %1}, %2;" : "=f"(lo), "=f"(hi) : "l"(v));
}
#define FMA2(d, a, b) asm("fma.rn.f32x2 %0, %1, %2, %0;" : "+l"(d) : "l"(a), "l"(b))

__global__ void __launch_bounds__(TPB, 2) epm_kernel(
    const float* __restrict__ q,
    const float* __restrict__ mem,
    float* __restrict__ out_ret,
    float* __restrict__ out_max,
    int nrows)
{
    extern __shared__ __align__(16) float sh[];
    float* qs    = sh;
    float* mem_t = sh + SM_MT;     // [c][m], 16B-aligned per c
    float* Wm    = sh + SM_W;      // [row][16] stride 20

    const int tid = threadIdx.x;
    const int blockRow = blockIdx.x * ROWS;
    const int nr1 = nrows - 1;

    // ---- Build mem_t [c][m] conflict-free via two-step transpose through qs ----
    {
        float* mem_s = qs;                       // temp: [m][c] stride 257
        #pragma unroll
        for (int i = 0; i < MITEMS * D / TPB; i++) {   // 16 coalesced LDG + dense STS
            int idx = tid + TPB * i;
            mem_s[(idx >> 8) * 257 + (idx & 255)] = mem[idx];
        }
        __syncthreads();
        const int m0 = tid & 15;                 // bank-spread transposed write
        const int c0 = tid >> 4;
        #pragma unroll
        for (int i = 0; i < 16; i++) {
            int c = c0 + 16 * i;
            mem_t[c * MITEMS + m0] = mem_s[m0 * 257 + c];
        }
        __syncthreads();
    }

    // ---- Dot phase: thread = row, item-pair-packed f32x2 accumulators ----
    const float4* qg = (const float4*)q;
    const int row8 = tid >> 3;      // 0..31
    const int c4   = tid & 7;       // 0..7
    const size_t gbase = (size_t)blockRow * (D / 4);

    float4 pf[8];
    // prefetch + stage chunk 0
    #pragma unroll
    for (int i = 0; i < 8; i++) {
        int rl = i * 32 + row8;
        int rg = blockRow + rl; rg = rg < nr1 ? rg : nr1;
        pf[i] = qg[(size_t)rg * (D / 4) + c4];
    }
    #pragma unroll
    for (int i = 0; i < 8; i++) {
        float* p = qs + (i * 32 + row8) * QSTR + c4 * 4;
        p[0] = pf[i].x; p[1] = pf[i].y; p[2] = pf[i].z; p[3] = pf[i].w;
    }
    __syncthreads();

    u64 acc[8];
    #pragma unroll
    for (int p = 0; p < 8; p++) acc[p] = 0ull;
    float ssq = 0.0f;
    const int qrow = tid * QSTR;

    #pragma unroll 1
    for (int ct = 0; ct < NCH; ct++) {
        if (ct + 1 < NCH) {                       // coalesced prefetch (nL=4)
            #pragma unroll
            for (int i = 0; i < 8; i++) {
                int rl = i * 32 + row8;
                int rg = blockRow + rl; rg = rg < nr1 ? rg : nr1;
                pf[i] = qg[(size_t)rg * (D / 4) + (ct + 1) * 8 + c4];
            }
        }
        const float* qb = qs + (ct & 1) * QBUF + qrow;
        #pragma unroll
        for (int c = 0; c < CHUNK; c++) {
            float qv = qb[c];                     // bank = row + c : conflict-free
            u64 qq = pack2(qv, qv);
            const ulonglong2* mt = (const ulonglong2*)(mem_t + (ct * CHUNK + c) * MITEMS);
            ulonglong2 v0 = mt[0], v1 = mt[1], v2 = mt[2], v3 = mt[3];  // broadcast
            ssq = fmaf(qv, qv, ssq);
            FMA2(acc[0], v0.x, qq); FMA2(acc[1], v0.y, qq);
            FMA2(acc[2], v1.x, qq); FMA2(acc[3], v1.y, qq);
            FMA2(acc[4], v2.x, qq); FMA2(acc[5], v2.y, qq);
            FMA2(acc[6], v3.x, qq); FMA2(acc[7], v3.y, qq);
        }
        if (ct + 1 < NCH) {
            float* buf = qs + ((ct + 1) & 1) * QBUF;
            #pragma unroll
            for (int i = 0; i < 8; i++) {
                float* p = buf + (i * 32 + row8) * QSTR + c4 * 4;
                p[0] = pf[i].x; p[1] = pf[i].y; p[2] = pf[i].z; p[3] = pf[i].w;
            }
        }
        __syncthreads();
    }

    // ---- Epilogue: normalize, top-4 (first-index ties), softmax -> W row ----
    {
        float s[MITEMS];
        #pragma unroll
        for (int p = 0; p < 8; p++) { unpack2(acc[p], s[2 * p], s[2 * p + 1]); }
        float inv = rsqrtf(fmaxf(ssq, 1e-24f)) * 10.0f;   // (1/|q|)/tau; mem unit-norm
        #pragma unroll
        for (int m = 0; m < MITEMS; m++) s[m] *= inv;

        float bw[4]; int bi[4];
        #pragma unroll
        for (int k = 0; k < 4; k++) {
            float best = NEG_BIG; int b = 0;
            #pragma unroll
            for (int m = 0; m < MITEMS; m++)
                if (s[m] > best) { best = s[m]; b = m; }
            bw[k] = best; bi[k] = b;
            #pragma unroll
            for (int m = 0; m < MITEMS; m++)
                s[m] = (m == b) ? NEG_BIG : s[m];
        }
        float e1 = __expf(bw[1] - bw[0]);
        float e2 = __expf(bw[2] - bw[0]);
        float e3 = __expf(bw[3] - bw[0]);
        float rden = 1.0f / (1.0f + e1 + e2 + e3);

        float* Wr = Wm + tid * WSTR;
        #pragma unroll
        for (int m = 0; m < MITEMS; m++) Wr[m] = 0.0f;
        Wr[bi[0]] = rden;
        Wr[bi[1]] = e1 * rden;
        Wr[bi[2]] = e2 * rden;
        Wr[bi[3]] = e3 * rden;

        int row_g = blockRow + tid;
        if (row_g < nrows) out_max[row_g] = bw[0];
    }
    __syncthreads();

    // ---- Dense blend from registers: out[r] = sum_m W[r][m] * mem[m][:] ----
    const int wid  = tid >> 5;
    const int lane = tid & 31;
    const ulonglong2* mg = (const ulonglong2*)mem;   // [m][64] float4-as-u64x2

    #pragma unroll 1
    for (int p = 0; p < 2; p++) {
        ulonglong2 V[MITEMS];                        // mem columns, register-resident
        #pragma unroll
        for (int m = 0; m < MITEMS; m++)
            V[m] = mg[m * (D / 4) + p * 32 + lane];

        #pragma unroll 2
        for (int j = 0; j < 32; j++) {
            int rl = wid * 32 + j;
            int row_g = blockRow + rl;
            const float4* Wp = (const float4*)(Wm + rl * WSTR);   // broadcast
            float4 w0 = Wp[0], w1 = Wp[1], w2 = Wp[2], w3 = Wp[3];
            float wv[16] = {w0.x, w0.y, w0.z, w0.w, w1.x, w1.y, w1.z, w1.w,
                            w2.x, w2.y, w2.z, w2.w, w3.x, w3.y, w3.z, w3.w};
            u64 o0 = 0ull, o1 = 0ull;
            #pragma unroll
            for (int m = 0; m < MITEMS; m++) {
                u64 wm = pack2(wv[m], wv[m]);
                FMA2(o0, V[m].x, wm);
                FMA2(o1, V[m].y, wm);
            }
            float4 o;
            unpack2(o0, o.x, o.y);
            unpack2(o1, o.z, o.w);
            if (row_g < nrows)
                ((float4*)(out_ret + (size_t)row_g * D))[p * 32 + lane] = o;
        }
    }
}

extern "C" void kernel_launch(void* const* d_in, const int* in_sizes, int n_in,
                              void* d_out, int out_size)
{
    const float* q   = (const float*)d_in[0];
    const float* mem = (const float*)d_in[1];
    int nrows = in_sizes[0] / D;              // 131072
    float* out_ret = (float*)d_out;
    float* out_max = out_ret + (size_t)nrows * D;

    cudaFuncSetAttribute(epm_kernel,
                         cudaFuncAttributeMaxDynamicSharedMemorySize, SMEM_BYTES);

    int grid = (nrows + ROWS - 1) / ROWS;     // 512
    epm_kernel<<<grid, TPB, SMEM_BYTES>>>(q, mem, out_ret, out_max, nrows);
}

// round 5
// speedup vs baseline: 1.5082x; 1.2820x over previous
#include <cuda_runtime.h>
#include <stdint.h>

#define D       256
#define MITEMS  16
#define TPB     128
#define RPT     4
#define ROWS    512          // rows per block
#define CHUNK   16           // dims per pipeline stage
#define NCH     16
#define QSTR    20           // q smem row stride (floats): 16B-aligned, LDS.128 conflict-free
#define QBUF    (ROWS * QSTR)        // 10240 floats per buffer
#define SM_MT   (2 * QBUF)           // mem_t offset: 20480
#define WSTR    20                   // W row stride (aliases qs buf0: 512*20 = 10240 <= QBUF)
#define SMEM_FLOATS (SM_MT + MITEMS * D)   // 24576 floats = 96 KB
#define SMEM_BYTES  (SMEM_FLOATS * 4)
#define NEG_BIG (-1e30f)

typedef unsigned long long u64;

__device__ __forceinline__ u64 pack2(float lo, float hi) {
    u64 r; asm("mov.b64 %0, {%1, %2};" : "=l"(r) : "f"(lo), "f"(hi)); return r;
}
__device__ __forceinline__ void unpack2(u64 v, float& lo, float& hi) {
    asm("mov.b64 {%0, %1}, %2;" : "=f"(lo), "=f"(hi) : "l"(v));
}
#define FMA2(d, a, b) asm("fma.rn.f32x2 %0, %1, %2, %0;" : "+l"(d) : "l"(a), "l"(b))
#define CP16(dst, src) \
    asm volatile("cp.async.cg.shared.global [%0], [%1], 16;" :: "r"(dst), "l"(src))
#define CPCOMMIT() asm volatile("cp.async.commit_group;")
#define CPWAIT(n)  asm volatile("cp.async.wait_group %0;" :: "n"(n))

__global__ void __launch_bounds__(TPB) epm_kernel(
    const float* __restrict__ q,
    const float* __restrict__ mem,
    float* __restrict__ out_ret,
    float* __restrict__ out_max,
    int nrows)
{
    extern __shared__ __align__(16) float sh[];
    float* qs    = sh;                 // 2 buffers of ROWS x QSTR
    float* mem_t = sh + SM_MT;         // [dim][16 items]
    float* Wm    = sh;                 // aliases qs buf0 (dead after dot)

    const int tid = threadIdx.x;
    const int blockRow = blockIdx.x * ROWS;
    const int nr1 = nrows - 1;
    const uint32_t qs_s = (uint32_t)__cvta_generic_to_shared(qs);

    // cp.async lane mapping: 8 rows x 64B per warp-instr
    const int rsub = tid >> 2;    // 0..31
    const int sub  = tid & 3;     // 16B slot within the 64B chunk row-segment

    // ---- issue chunk 0 immediately (overlap DRAM latency with mem_t build) ----
    {
        #pragma unroll
        for (int j = 0; j < 16; j++) {
            int rl = rsub + 32 * j;
            int rg = blockRow + rl; rg = rg < nr1 ? rg : nr1;
            const float* src = q + (size_t)rg * D + sub * 4;
            uint32_t dst = qs_s + (uint32_t)(rl * QSTR + sub * 4) * 4u;
            CP16(dst, src);
        }
        CPCOMMIT();
    }

    // ---- build mem_t [dim][item] via two-step transpose (temp in qs buf1) ----
    {
        float* tmp = qs + QBUF;                 // 16 x 257 = 4112 floats, fits buf1
        #pragma unroll
        for (int i = 0; i < (MITEMS * D) / TPB; i++) {   // 32 coalesced LDG
            int idx = tid + TPB * i;
            tmp[(idx >> 8) * 257 + (idx & 255)] = mem[idx];
        }
        __syncthreads();
        const int m0 = tid & 15;
        const int c0 = tid >> 4;                // 0..7
        #pragma unroll
        for (int i = 0; i < 32; i++) {
            int c = c0 + 8 * i;
            mem_t[c * MITEMS + m0] = tmp[m0 * 257 + c];
        }
        __syncthreads();                        // tmp reads done -> buf1 reusable
    }

    // ---- issue chunk 1 into buf1 ----
    {
        #pragma unroll
        for (int j = 0; j < 16; j++) {
            int rl = rsub + 32 * j;
            int rg = blockRow + rl; rg = rg < nr1 ? rg : nr1;
            const float* src = q + (size_t)rg * D + CHUNK + sub * 4;
            uint32_t dst = qs_s + (uint32_t)(QBUF + rl * QSTR + sub * 4) * 4u;
            CP16(dst, src);
        }
        CPCOMMIT();
    }

    // ---- dot mainloop: 4 rows/thread, item-pair-packed f32x2 ----
    u64 acc[RPT][8];
    float ssq[RPT];
    #pragma unroll
    for (int r = 0; r < RPT; r++) {
        ssq[r] = 0.0f;
        #pragma unroll
        for (int p = 0; p < 8; p++) acc[r][p] = 0ull;
    }

    #pragma unroll 1
    for (int ct = 0; ct < NCH; ct++) {
        if (ct + 1 < NCH) { CPWAIT(1); } else { CPWAIT(0); }
        __syncthreads();                        // chunk ct visible to all

        const float* qb = qs + (ct & 1) * QBUF;
        #pragma unroll
        for (int gr = 0; gr < 4; gr++) {        // 4-dim groups
            float qa[RPT][4];
            #pragma unroll
            for (int r = 0; r < RPT; r++) {
                float4 f = *(const float4*)(qb + (tid + 128 * r) * QSTR + 4 * gr);
                qa[r][0] = f.x; qa[r][1] = f.y; qa[r][2] = f.z; qa[r][3] = f.w;
            }
            #pragma unroll
            for (int c = 0; c < 4; c++) {
                const ulonglong2* mt =
                    (const ulonglong2*)(mem_t + (ct * CHUNK + gr * 4 + c) * MITEMS);
                ulonglong2 v0 = mt[0], v1 = mt[1], v2 = mt[2], v3 = mt[3];
                u64 mp[8] = {v0.x, v0.y, v1.x, v1.y, v2.x, v2.y, v3.x, v3.y};
                #pragma unroll
                for (int r = 0; r < RPT; r++) {
                    float qv = qa[r][c];
                    u64 qq = pack2(qv, qv);
                    ssq[r] = fmaf(qv, qv, ssq[r]);
                    #pragma unroll
                    for (int p = 0; p < 8; p++) FMA2(acc[r][p], mp[p], qq);
                }
            }
        }
        __syncthreads();                        // buf ct&1 reads done everywhere
        if (ct + 2 < NCH) {                     // refill the just-freed buffer
            #pragma unroll
            for (int j = 0; j < 16; j++) {
                int rl = rsub + 32 * j;
                int rg = blockRow + rl; rg = rg < nr1 ? rg : nr1;
                const float* src = q + (size_t)rg * D + (ct + 2) * CHUNK + sub * 4;
                uint32_t dst = qs_s + (uint32_t)((ct & 1) * QBUF + rl * QSTR + sub * 4) * 4u;
                CP16(dst, src);
            }
            CPCOMMIT();
        }
    }

    // ---- epilogue: 4 rows/thread -> W rows (stride 20, aliases buf0) ----
    #pragma unroll
    for (int g = 0; g < RPT; g++) {
        float s[MITEMS];
        #pragma unroll
        for (int p = 0; p < 8; p++) { unpack2(acc[g][p], s[2 * p], s[2 * p + 1]); }
        float inv = rsqrtf(fmaxf(ssq[g], 1e-24f)) * 10.0f;  // (1/|q|)/tau; mem unit-norm
        #pragma unroll
        for (int m = 0; m < MITEMS; m++) s[m] *= inv;

        float bw[4]; int bi[4];
        #pragma unroll
        for (int k = 0; k < 4; k++) {
            float best = NEG_BIG; int b = 0;
            #pragma unroll
            for (int m = 0; m < MITEMS; m++)
                if (s[m] > best) { best = s[m]; b = m; }   // strict > : first index ties
            bw[k] = best; bi[k] = b;
            #pragma unroll
            for (int m = 0; m < MITEMS; m++)
                s[m] = (m == b) ? NEG_BIG : s[m];
        }
        float e1 = __expf(bw[1] - bw[0]);
        float e2 = __expf(bw[2] - bw[0]);
        float e3 = __expf(bw[3] - bw[0]);
        float rden = 1.0f / (1.0f + e1 + e2 + e3);

        int rl = tid + 128 * g;
        float* Wr = Wm + rl * WSTR;
        #pragma unroll
        for (int m = 0; m < MITEMS; m++) Wr[m] = 0.0f;
        Wr[bi[0]] = rden;
        Wr[bi[1]] = e1 * rden;
        Wr[bi[2]] = e2 * rden;
        Wr[bi[3]] = e3 * rden;

        int row_g = blockRow + rl;
        if (row_g < nrows) out_max[row_g] = bw[0];
    }
    __syncthreads();

    // ---- dense blend from registers: out[r] = sum_m W[r][m] * mem[m][:] ----
    const int wid  = tid >> 5;
    const int lane = tid & 31;
    const ulonglong2* mg = (const ulonglong2*)mem;    // 64 x 16B per item row

    ulonglong2 V[2 * MITEMS];                         // full memory bank slice per lane
    #pragma unroll
    for (int m = 0; m < MITEMS; m++) {
        V[2 * m    ] = mg[m * (D / 4) + lane];        // dims [lane*4 .. )
        V[2 * m + 1] = mg[m * (D / 4) + 32 + lane];   // dims [128 + lane*4 .. )
    }

    #pragma unroll 2
    for (int j = 0; j < ROWS / 4; j++) {              // 128 rows per warp
        int rl = wid * (ROWS / 4) + j;
        int row_g = blockRow + rl;
        const float4* Wp = (const float4*)(Wm + rl * WSTR);   // broadcast
        float4 w0 = Wp[0], w1 = Wp[1], w2 = Wp[2], w3 = Wp[3];
        float wv[16] = {w0.x, w0.y, w0.z, w0.w, w1.x, w1.y, w1.z, w1.w,
                        w2.x, w2.y, w2.z, w2.w, w3.x, w3.y, w3.z, w3.w};
        u64 o0 = 0ull, o1 = 0ull, o2 = 0ull, o3 = 0ull;
        #pragma unroll
        for (int m = 0; m < MITEMS; m++) {
            u64 wm = pack2(wv[m], wv[m]);
            FMA2(o0, V[2 * m    ].x, wm);
            FMA2(o1, V[2 * m    ].y, wm);
            FMA2(o2, V[2 * m + 1].x, wm);
            FMA2(o3, V[2 * m + 1].y, wm);
        }
        if (row_g < nrows) {
            ulonglong2* op = (ulonglong2*)(out_ret + (size_t)row_g * D);
            ulonglong2 r0; r0.x = o0; r0.y = o1;
            ulonglong2 r1; r1.x = o2; r1.y = o3;
            op[lane]      = r0;
            op[32 + lane] = r1;
        }
    }
}

extern "C" void kernel_launch(void* const* d_in, const int* in_sizes, int n_in,
                              void* d_out, int out_size)
{
    const float* q   = (const float*)d_in[0];
    const float* mem = (const float*)d_in[1];
    int nrows = in_sizes[0] / D;              // 131072
    float* out_ret = (float*)d_out;
    float* out_max = out_ret + (size_t)nrows * D;

    cudaFuncSetAttribute(epm_kernel,
                         cudaFuncAttributeMaxDynamicSharedMemorySize, SMEM_BYTES);

    int grid = (nrows + ROWS - 1) / ROWS;     // 256
    epm_kernel<<<grid, TPB, SMEM_BYTES>>>(q, mem, out_ret, out_max, nrows);
}